// round 1
// baseline (speedup 1.0000x reference)
#include <cuda_runtime.h>
#include <cstdint>

// LIF recurrence: T=64 sequential steps, B*N = 524288 independent lanes.
//   h = v + (x - v) / 2
//   s = (h >= 1.0f) ? 1 : 0
//   v = s ? 0 : h
// Memory bound: 268 MB total traffic. One thread owns 4 lanes (float4),
// software-pipelined 2 deep for MLP.

static constexpr int T = 64;

__global__ void __launch_bounds__(256) lif_kernel(const float4* __restrict__ x,
                                                  float4* __restrict__ out,
                                                  int lanes4)  // B*N/4 per timestep
{
    int i = blockIdx.x * blockDim.x + threadIdx.x;
    if (i >= lanes4) return;

    float4 v = make_float4(0.f, 0.f, 0.f, 0.f);

    // software pipeline: prefetch next timestep's load while computing current
    float4 xt = x[i];

    #pragma unroll 4
    for (int t = 0; t < T; ++t) {
        float4 xnext;
        if (t + 1 < T) xnext = x[(size_t)(t + 1) * lanes4 + i];

        float4 h, s;
        h.x = v.x + (xt.x - v.x) * 0.5f;
        h.y = v.y + (xt.y - v.y) * 0.5f;
        h.z = v.z + (xt.z - v.z) * 0.5f;
        h.w = v.w + (xt.w - v.w) * 0.5f;

        s.x = (h.x >= 1.0f) ? 1.0f : 0.0f;
        s.y = (h.y >= 1.0f) ? 1.0f : 0.0f;
        s.z = (h.z >= 1.0f) ? 1.0f : 0.0f;
        s.w = (h.w >= 1.0f) ? 1.0f : 0.0f;

        v.x = (h.x >= 1.0f) ? 0.0f : h.x;
        v.y = (h.y >= 1.0f) ? 0.0f : h.y;
        v.z = (h.z >= 1.0f) ? 0.0f : h.z;
        v.w = (h.w >= 1.0f) ? 0.0f : h.w;

        out[(size_t)t * lanes4 + i] = s;

        xt = xnext;
    }
}

extern "C" void kernel_launch(void* const* d_in, const int* in_sizes, int n_in,
                              void* d_out, int out_size)
{
    const float4* x = (const float4*)d_in[0];
    float4* out = (float4*)d_out;

    // total elements = T * B * N; lanes per timestep = total / T; float4 lanes:
    int total = in_sizes[0];
    int lanes = total / T;        // 524288
    int lanes4 = lanes / 4;       // 131072

    int threads = 256;
    int blocks = (lanes4 + threads - 1) / threads;
    lif_kernel<<<blocks, threads>>>(x, out, lanes4);
}